// round 3
// baseline (speedup 1.0000x reference)
#include <cuda_runtime.h>
#include <math_constants.h>

#define B      64
#define C      2048
#define FM     14
#define NPIX   196
#define NCHUNK 16
#define CCHUNK 128   // C / NCHUNK
#define TW     837
#define MAXPW  12    // max windows per lane (ceil(361/32))

// scratch for per-chunk partial channel sums (no cudaMalloc allowed)
__device__ float g_partial[NCHUNK * B * NPIX];

__constant__ int d_RH[11]   = {4,3,5,6,5,7,8,6,10,7,9};
__constant__ int d_RW[11]   = {4,5,3,6,7,5,8,10,6,9,7};
__constant__ int d_WOFF[12] = {0,121,241,361,442,522,602,651,696,741,789,837};
__constant__ int d_GR0[3]   = {0, 3, 6};
__constant__ int d_GOFF[3]  = {0, 361, 602};
__constant__ int d_GW[3]    = {361, 241, 235};
__constant__ int d_GN[3]    = {3, 2, 1};
__constant__ int d_GSLOT[3] = {0, 3, 5};

// ---------------------------------------------------------------------------
// Kernel 1: channel-chunk reduction.  grid = (NCHUNK, B), block = 196.
// ~8 TB/s achieved — at HBM spec; do not touch.
// ---------------------------------------------------------------------------
__global__ void __launch_bounds__(196) appm_reduce_kernel(const float* __restrict__ x)
{
    const int chunk = blockIdx.x;
    const int b     = blockIdx.y;
    const int t     = threadIdx.x;
    const int q     = t % 49;
    const int cw    = t / 49;

    const float4* base = reinterpret_cast<const float4*>(x)
                       + ((size_t)b * C + (size_t)chunk * CCHUNK) * 49;

    float4 acc = make_float4(0.f, 0.f, 0.f, 0.f);
#pragma unroll 8
    for (int c = cw; c < CCHUNK; c += 4) {
        float4 v = __ldcs(base + (size_t)c * 49 + q);
        acc.x += v.x; acc.y += v.y; acc.z += v.z; acc.w += v.w;
    }

    __shared__ float s[NPIX];
    if (t < NPIX) s[t] = 0.f;
    __syncthreads();
    atomicAdd(&s[q * 4 + 0], acc.x);
    atomicAdd(&s[q * 4 + 1], acc.y);
    atomicAdd(&s[q * 4 + 2], acc.z);
    atomicAdd(&s[q * 4 + 3], acc.w);
    __syncthreads();
    if (t < NPIX)
        g_partial[(chunk * B + b) * NPIX + t] = s[t];
}

// window index (global) -> coords
__device__ __forceinline__ void win_coords(int gw, int r0,
                                           float& x0, float& y0, float& x1, float& y1)
{
    int r = r0;
    while (gw >= d_WOFF[r + 1]) r++;
    const int loc = gw - d_WOFF[r];
    const int rh  = d_RH[r], rw = d_RW[r];
    const int nw  = FM - rw + 1;
    const int i   = loc / nw, j = loc % nw;
    x0 = (float)(j * 32);
    y0 = (float)(i * 32);
    x1 = (float)((j + rw) * 32 - 1);
    y1 = (float)((i + rh) * 32 - 1);
}

// ---------------------------------------------------------------------------
// Kernel 2: per-batch scores + 3 concurrent warp-private NMS groups.
// grid = B, block = 224 (7 warps; warps 0..2 do NMS, one group each).
// Output layout (fp32): [B*6 indices][B*6 scores][B*837 all_scores]
// ---------------------------------------------------------------------------
__global__ void __launch_bounds__(224) appm_nms_kernel(float* __restrict__ out)
{
    const int b    = blockIdx.x;
    const int tid  = threadIdx.x;
    const int lane = tid & 31;
    const int wid  = tid >> 5;

    __shared__ float  y[NPIX];
    __shared__ double SAT[FM + 1][FM + 1];
    __shared__ float  sc[TW];

    // ---- sum partials ----
    if (tid < NPIX) {
        float acc = 0.f;
#pragma unroll
        for (int ch = 0; ch < NCHUNK; ch++)
            acc += g_partial[(ch * B + b) * NPIX + tid];
        y[tid] = acc;
    }
    if (tid < FM + 1) { SAT[0][tid] = 0.0; SAT[tid][0] = 0.0; }
    __syncthreads();

    // ---- integral image (double; matches reference to ~2e-7) ----
    if (tid < FM) {
        double r = 0.0;
#pragma unroll
        for (int j = 0; j < FM; j++) {
            r += (double)y[tid * FM + j];
            SAT[tid + 1][j + 1] = r;
        }
    }
    __syncthreads();
    if (tid < FM) {
        double r = 0.0;
#pragma unroll
        for (int i = 1; i <= FM; i++) {
            r += SAT[i][tid + 1];
            SAT[i][tid + 1] = r;
        }
    }
    __syncthreads();

    // ---- all 837 window scores, once ----
    for (int w = tid; w < TW; w += 224) {
        int r = 0;
        while (w >= d_WOFF[r + 1]) r++;
        const int loc = w - d_WOFF[r];
        const int rh  = d_RH[r], rw = d_RW[r];
        const int nw  = FM - rw + 1;
        const int i   = loc / nw, j = loc % nw;
        const float s = (float)(SAT[i + rh][j + rw] - SAT[i][j + rw]
                              - SAT[i + rh][j]      + SAT[i][j]);
        const float sv = s / (float)(rh * rw);
        sc[w] = sv;
        out[2 * B * 6 + (size_t)b * TW + w] = sv;   // all_scores
    }
    __syncthreads();

    if (wid >= 3) return;   // warps 3..6 done

    // ---- warp-private greedy NMS: warp `wid` handles group `wid` ----
    const int g     = wid;
    const int goff  = d_GOFF[g];
    const int W     = d_GW[g];
    const int nsel  = d_GN[g];
    const int slot0 = d_GSLOT[g];
    const int r0    = d_GR0[g];

    float lsc[MAXPW], lx0[MAXPW], ly0[MAXPW], lx1[MAXPW], ly1[MAXPW], lar[MAXPW];
    unsigned vmask = 0;
#pragma unroll
    for (int k = 0; k < MAXPW; k++) {
        const int w = lane + 32 * k;
        if (w < W) {
            lsc[k] = sc[goff + w];
            win_coords(goff + w, r0, lx0[k], ly0[k], lx1[k], ly1[k]);
            lar[k] = (lx1[k] - lx0[k] + 1.f) * (ly1[k] - ly0[k] + 1.f);
            vmask |= 1u << k;
        }
    }

    int last = 0;
    for (int step = 0; step < nsel; step++) {
        // local argmax (ascending k => lowest window index on tie within lane)
        float bs = -CUDART_INF_F;
        int   bi = 0x7fffffff;
#pragma unroll
        for (int k = 0; k < MAXPW; k++) {
            if ((vmask >> k) & 1u) {
                if (lsc[k] > bs) { bs = lsc[k]; bi = lane + 32 * k; }
            }
        }
        // butterfly reduce: all lanes converge; tie-break lowest global index
#pragma unroll
        for (int o = 16; o > 0; o >>= 1) {
            const float s2 = __shfl_xor_sync(0xffffffffu, bs, o);
            const int   i2 = __shfl_xor_sync(0xffffffffu, bi, o);
            if (s2 > bs || (s2 == bs && i2 < bi)) { bs = s2; bi = i2; }
        }
        const bool anyv = bs > -CUDART_INF_F;
        const int  idx  = anyv ? bi : last;      // fallback: repeat last

        if (lane == 0) {
            out[(size_t)b * 6 + slot0 + step]         = (float)(goff + idx);
            out[B * 6 + (size_t)b * 6 + slot0 + step] = sc[goff + idx];
        }

        if (anyv) {
            float sx0, sy0, sx1, sy1;
            win_coords(goff + idx, r0, sx0, sy0, sx1, sy1);   // uniform across warp
            const float sarea = (sx1 - sx0 + 1.f) * (sy1 - sy0 + 1.f);
#pragma unroll
            for (int k = 0; k < MAXPW; k++) {
                if ((vmask >> k) & 1u) {
                    const float lx = fmaxf(lx0[k], sx0);
                    const float ly = fmaxf(ly0[k], sy0);
                    const float rx = fminf(lx1[k], sx1);
                    const float ry = fminf(ly1[k], sy1);
                    const float wx = rx - lx + 1.f;
                    const float wy = ry - ly + 1.f;
                    const float inter = (wx < 0.f || wy < 0.f) ? 0.f : wx * wy;
                    const float iou   = inter / (lar[k] + sarea - inter);
                    if (iou > 0.25f) vmask &= ~(1u << k);   // self-IoU=1 clears sel
                }
            }
        }
        last = idx;
    }
}

extern "C" void kernel_launch(void* const* d_in, const int* in_sizes, int n_in,
                              void* d_out, int out_size)
{
    const float* x = (const float*)d_in[0];
    float* out = (float*)d_out;
    appm_reduce_kernel<<<dim3(NCHUNK, B), 196>>>(x);
    appm_nms_kernel<<<B, 224>>>(out);
}